// round 14
// baseline (speedup 1.0000x reference)
#include <cuda_runtime.h>
#include <cuda_fp16.h>
#include <cstdint>

#define NBATCH 16
#define TLEN   1024
#define DHID   768
#define NCTA   48
#define NTHR   512
#define NSTEP  2048

// ---------------- global scratch (no device allocation allowed) ----------------
// Self-validating h broadcast: per parity, per CTA 48 chunks (16 batches x 3).
// chunk uint4 = {h2(d0,d1), h2(d2,d3), h2(d4,d5), tag}
__device__ __align__(16) uint4 g_hch[2][NCTA * 48];

__global__ void init_kernel(const float* __restrict__ states) {
    int i = blockIdx.x * blockDim.x + threadIdx.x;
    if (i < NCTA * 48) {
        int cta = i / 48, r = i - cta * 48;
        int b = r / 3, j = r - b * 3;
        int d0 = cta * 16 + 6 * j;
        const float* hp = states + b * DHID + d0;
        int nv = (j == 2) ? 4 : 6;
        float v[6];
        #pragma unroll
        for (int q = 0; q < 6; ++q) v[q] = (q < nv) ? hp[q] : 0.f;
        uint4 pkt;
        __half2 p0 = __floats2half2_rn(v[0], v[1]);
        __half2 p1 = __floats2half2_rn(v[2], v[3]);
        __half2 p2 = __floats2half2_rn(v[4], v[5]);
        pkt.x = *reinterpret_cast<uint32_t*>(&p0);
        pkt.y = *reinterpret_cast<uint32_t*>(&p1);
        pkt.z = *reinterpret_cast<uint32_t*>(&p2);
        pkt.w = 0u;  // tag for step 0
        g_hch[0][i] = pkt;
    }
}

// ---------------- helpers ----------------
__device__ __forceinline__ float fast_sigmoid(float x) {
    return 1.f / (1.f + __expf(-x));
}
__device__ __forceinline__ float fast_tanh(float x) {
    float ax = fabsf(x);
    float e  = __expf(-2.f * ax);
    float r  = (1.f - e) / (1.f + e);
    return copysignf(r, x);
}
__device__ __forceinline__ uint4 ldcg_v4(const uint4* p) {
    uint4 v;
    asm volatile("ld.global.cg.v4.u32 {%0,%1,%2,%3}, [%4];"
                 : "=r"(v.x), "=r"(v.y), "=r"(v.z), "=r"(v.w) : "l"(p));
    return v;
}
__device__ __forceinline__ void stcg_v4(uint4* p, uint4 v) {
    asm volatile("st.global.cg.v4.u32 [%0], {%1,%2,%3,%4};"
                 :: "l"(p), "r"(v.x), "r"(v.y), "r"(v.z), "r"(v.w) : "memory");
}
__device__ __forceinline__ uint32_t pack_h2(float lo, float hi) {
    __half2 h = __floats2half2_rn(lo, hi);
    return *reinterpret_cast<uint32_t*>(&h);
}
__device__ __forceinline__ void mma16816(float* d, const uint32_t* a, const uint32_t* b) {
    asm volatile(
        "mma.sync.aligned.m16n8k16.row.col.f32.f16.f16.f32 "
        "{%0,%1,%2,%3}, {%4,%5,%6,%7}, {%8,%9}, {%0,%1,%2,%3};"
        : "+f"(d[0]), "+f"(d[1]), "+f"(d[2]), "+f"(d[3])
        : "r"(a[0]), "r"(a[1]), "r"(a[2]), "r"(a[3]), "r"(b[0]), "r"(b[1]));
}

// SMEM: red[16 warps][64 rows][17] floats = 69632 B, then htile [16 b][1552 B]
#define REDW    1088          // 64*17 floats per warp
#define RED_BYTES 69632
#define HSTRIDE 1552          // bytes per batch row (768*2 + 16 pad)
#define SMEM_TOTAL (RED_BYTES + NBATCH * HSTRIDE)

__global__ void __launch_bounds__(NTHR, 1)
lstm_kernel(const float* __restrict__ states,
            const float* __restrict__ Wx0, const float* __restrict__ R0, const float* __restrict__ bias0,
            const float* __restrict__ Wx1, const float* __restrict__ R1, const float* __restrict__ bias1,
            float* __restrict__ out)
{
    extern __shared__ __align__(16) char smem[];
    float* red  = (float*)smem;
    char* htile = smem + RED_BYTES;

    const int tid  = threadIdx.x;
    const int wid  = tid >> 5;    // 0..15
    const int lane = tid & 31;
    const int gid  = lane >> 2;   // mma group (row / n)
    const int tig  = lane & 3;    // thread-in-group (k)
    const int cta  = blockIdx.x;
    const int kbase = wid * 48;   // this warp's K slice -> producer CTAs [3*wid, 3*wid+3)

    // epilogue mapping (tid < 256): b = tid>>4, e_local = tid&15
    const int eb = tid >> 4;
    const int el = tid & 15;
    const int eg = cta * 16 + el;

    // register-resident state
    uint32_t areg[4][3][4];       // A fragments: [m-tile][k-tile][reg]
    float    bias[4];
    float    creg = 0.f;

    if (tid < 256) {
        creg = states[NBATCH * DHID + eb * DHID + eg];
    }

    for (int s = 0; s < NSTEP; ++s) {
        const int layer = s >> 10;
        const int t     = s & 1023;
        const float* Wx = layer ? Wx1 : Wx0;

        // ---- per-layer setup: A fragments (R slice) + bias ----
        if (t == 0) {
            const float* R  = layer ? R1 : R0;
            const float* bi = layer ? bias1 : bias0;
            #pragma unroll
            for (int mt = 0; mt < 4; ++mt) {
                const int l0 = mt * 16 + gid;        // local rows l0, l0+8
                const int l1 = l0 + 8;
                const int g0 = l0 >> 4, e0 = cta * 16 + (l0 & 15);
                const int g1 = l1 >> 4, e1 = cta * 16 + (l1 & 15);
                const float* p0 = R + (size_t)g0 * (DHID * DHID) + e0;
                const float* p1 = R + (size_t)g1 * (DHID * DHID) + e1;
                #pragma unroll
                for (int kt = 0; kt < 3; ++kt) {
                    const int k0 = kbase + kt * 16 + tig * 2;
                    areg[mt][kt][0] = pack_h2(__ldg(p0 + (size_t)(k0    ) * DHID),
                                              __ldg(p0 + (size_t)(k0 + 1) * DHID));
                    areg[mt][kt][1] = pack_h2(__ldg(p1 + (size_t)(k0    ) * DHID),
                                              __ldg(p1 + (size_t)(k0 + 1) * DHID));
                    areg[mt][kt][2] = pack_h2(__ldg(p0 + (size_t)(k0 + 8) * DHID),
                                              __ldg(p0 + (size_t)(k0 + 9) * DHID));
                    areg[mt][kt][3] = pack_h2(__ldg(p1 + (size_t)(k0 + 8) * DHID),
                                              __ldg(p1 + (size_t)(k0 + 9) * DHID));
                }
            }
            if (tid < 256) {
                #pragma unroll
                for (int g = 0; g < 4; ++g)
                    bias[g] = __ldg(bi + g * DHID + eg);
            }
        }

        // ---- Wx prefetch (DRAM latency hides behind the poll) ----
        float wx[4];
        if (tid < 256) {
            const float* wp = Wx + (size_t)eb * (TLEN * 4 * DHID) + (size_t)t * 3072 + eg;
            #pragma unroll
            for (int g = 0; g < 4; ++g)
                wx[g] = __ldcs(wp + g * DHID);
        }

        // ---- poll this warp's 144 chunks (lanes 0..23, 6 each): data IS the flag ----
        uint4 ch[6];
        {
            const unsigned want = (unsigned)s;
            const uint4* cb = g_hch[s & 1] + wid * 144 + lane * 6;
            unsigned ok = (lane >= 24) ? 1u : 0u;
            do {
                if (!ok) {
                    ok = 1u;
                    #pragma unroll
                    for (int q = 0; q < 6; ++q) {
                        ch[q] = ldcg_v4(cb + q);
                        ok &= (ch[q].w == want) ? 1u : 0u;
                    }
                }
            } while (__ballot_sync(0xffffffffu, ok) != 0xffffffffu);
        }

        // ---- stage chunks into the warp's htile column slice ----
        if (lane < 24) {
            #pragma unroll
            for (int q = 0; q < 6; ++q) {
                const int cid   = lane * 6 + q;
                const int p_rel = cid / 48;
                const int r     = cid - p_rel * 48;
                const int b     = r / 3;
                const int j     = r - b * 3;
                const int d0    = (3 * wid + p_rel) * 16 + 6 * j;
                uint32_t* dst = (uint32_t*)(htile + b * HSTRIDE + d0 * 2);
                dst[0] = ch[q].x;
                dst[1] = ch[q].y;
                if (j < 2) dst[2] = ch[q].z;
            }
        }
        __syncwarp();

        // ---- MMA: partial D[64,16] over this warp's 48-dim K slice ----
        float acc[4][2][4];
        #pragma unroll
        for (int mt = 0; mt < 4; ++mt)
            #pragma unroll
            for (int nt = 0; nt < 2; ++nt)
                #pragma unroll
                for (int r = 0; r < 4; ++r)
                    acc[mt][nt][r] = 0.f;
        #pragma unroll
        for (int kt = 0; kt < 3; ++kt) {
            const int k0 = kbase + kt * 16 + tig * 2;
            uint32_t bf[2][2];
            #pragma unroll
            for (int nt = 0; nt < 2; ++nt) {
                const char* hp = htile + (nt * 8 + gid) * HSTRIDE + k0 * 2;
                bf[nt][0] = *(const uint32_t*)(hp);
                bf[nt][1] = *(const uint32_t*)(hp + 16);
            }
            #pragma unroll
            for (int mt = 0; mt < 4; ++mt)
                #pragma unroll
                for (int nt = 0; nt < 2; ++nt)
                    mma16816(acc[mt][nt], areg[mt][kt], bf[nt]);
        }

        // ---- partials to SMEM for cross-warp K reduction ----
        {
            float* rp = red + wid * REDW;
            #pragma unroll
            for (int mt = 0; mt < 4; ++mt) {
                const int l0 = mt * 16 + gid;
                #pragma unroll
                for (int nt = 0; nt < 2; ++nt) {
                    const int n0 = nt * 8 + tig * 2;
                    rp[(l0    ) * 17 + n0    ] = acc[mt][nt][0];
                    rp[(l0    ) * 17 + n0 + 1] = acc[mt][nt][1];
                    rp[(l0 + 8) * 17 + n0    ] = acc[mt][nt][2];
                    rp[(l0 + 8) * 17 + n0 + 1] = acc[mt][nt][3];
                }
            }
        }
        // all warps' polls passed before this barrier -> safe to publish after it
        __syncthreads();

        // ---- epilogue (tid<256): reduce, activations, cell update, publish ----
        if (tid < 256) {
            float gate[4];
            #pragma unroll
            for (int g = 0; g < 4; ++g) {
                float v = wx[g] + bias[g];
                const int li = g * 16 + el;
                #pragma unroll
                for (int w = 0; w < 16; ++w)
                    v += red[w * REDW + li * 17 + eb];
                gate[g] = v;
            }
            const float iv = fast_sigmoid(gate[0]);
            const float fv = fast_sigmoid(gate[1]);
            const float zv = fast_tanh(gate[2]);
            const float ov = fast_sigmoid(gate[3]);
            creg = fv * creg + iv * zv;
            const float hv = ov * fast_tanh(creg);

            // gather 6 consecutive dims within the warp (same batch) and publish
            const float v1 = __shfl_down_sync(0xffffffffu, hv, 1);
            const float v2 = __shfl_down_sync(0xffffffffu, hv, 2);
            const float v3 = __shfl_down_sync(0xffffffffu, hv, 3);
            const float v4 = __shfl_down_sync(0xffffffffu, hv, 4);
            const float v5 = __shfl_down_sync(0xffffffffu, hv, 5);
            if (el == 0 || el == 6 || el == 12) {
                const int j = el / 6;
                uint4 pkt;
                if (j < 2) {
                    pkt.x = pack_h2(hv, v1);
                    pkt.y = pack_h2(v2, v3);
                    pkt.z = pack_h2(v4, v5);
                } else {
                    pkt.x = pack_h2(hv, v1);
                    pkt.y = pack_h2(v2, v3);
                    pkt.z = 0u;
                }
                pkt.w = (unsigned)(s + 1);
                stcg_v4(&g_hch[(s + 1) & 1][cta * 48 + eb * 3 + j], pkt);
            }

            // layer-2 outputs (streaming, off the critical chain)
            if (layer) {
                float* po = out + (size_t)t * 24576 + eb * DHID + eg;
                __stcs(po,         hv);
                __stcs(po + 12288, creg);
                if (t == TLEN - 1) {
                    float* pl = out + (size_t)25165824 + eb * DHID + eg;
                    __stcs(pl,                 hv);    // last_h: h
                    __stcs(pl + 12288,         creg);  // last_h: c
                    __stcs(pl + 24576,         hv);    // out: h
                    __stcs(pl + 24576 + 12288, creg);  // out: c
                }
            }
        }
        __syncthreads();   // red[] reads done before next step's STS
    }
}

extern "C" void kernel_launch(void* const* d_in, const int* in_sizes, int n_in,
                              void* d_out, int out_size) {
    (void)in_sizes; (void)n_in; (void)out_size;
    const float* states = (const float*)d_in[0];
    const float* Wx0    = (const float*)d_in[1];
    const float* R0     = (const float*)d_in[2];
    const float* b0     = (const float*)d_in[3];
    const float* Wx1    = (const float*)d_in[4];
    const float* R1     = (const float*)d_in[5];
    const float* b1     = (const float*)d_in[6];
    float* out = (float*)d_out;

    cudaFuncSetAttribute(lstm_kernel, cudaFuncAttributeMaxDynamicSharedMemorySize, SMEM_TOTAL);
    init_kernel<<<12, 256>>>(states);
    lstm_kernel<<<NCTA, NTHR, SMEM_TOTAL>>>(states, Wx0, R0, b0, Wx1, R1, b1, out);
}

// round 15
// speedup vs baseline: 1.1359x; 1.1359x over previous
#include <cuda_runtime.h>
#include <cuda_fp16.h>
#include <cstdint>

#define NBATCH 16
#define TLEN   1024
#define DHID   768
#define NCTA   96
#define NSTEP  2048
#define NTHR   256

// ---------------- global scratch (no device allocation allowed) ----------------
__device__ __align__(16) __half g_hbuf[2][NBATCH * DHID];  // h double buffer, fp16 [b][d]
__device__ int g_flag[NCTA * 32];                          // one flag per CTA, one per 128B line

__global__ void init_kernel(const float* __restrict__ states) {
    int i = blockIdx.x * blockDim.x + threadIdx.x;
    if (i < NBATCH * DHID) g_hbuf[0][i] = __float2half_rn(states[i]);
    if (i < NCTA * 32) g_flag[i] = 0;
}

// ---------------- helpers ----------------
__device__ __forceinline__ float fast_sigmoid(float x) {
    return 1.f / (1.f + __expf(-x));
}
__device__ __forceinline__ float fast_tanh(float x) {
    float ax = fabsf(x);
    float e  = __expf(-2.f * ax);
    float r  = (1.f - e) / (1.f + e);
    return copysignf(r, x);
}
__device__ __forceinline__ uint32_t ldcg_b32(const void* p) {
    uint32_t v;
    asm volatile("ld.global.cg.b32 %0, [%1];" : "=r"(v) : "l"(p));
    return v;
}
__device__ __forceinline__ uint32_t pack_h2(float lo, float hi) {
    __half2 h = __floats2half2_rn(lo, hi);
    return *reinterpret_cast<uint32_t*>(&h);
}
__device__ __forceinline__ void mma16816(float* d, const uint32_t* a, const uint32_t* b) {
    asm volatile(
        "mma.sync.aligned.m16n8k16.row.col.f32.f16.f16.f32 "
        "{%0,%1,%2,%3}, {%4,%5,%6,%7}, {%8,%9}, {%0,%1,%2,%3};"
        : "+f"(d[0]), "+f"(d[1]), "+f"(d[2]), "+f"(d[3])
        : "r"(a[0]), "r"(a[1]), "r"(a[2]), "r"(a[3]), "r"(b[0]), "r"(b[1]));
}

// red[parity][w][l][b]: 8 warps, 32 local gate-rows, b padded to 17
#define REDW 544  // 32*17 floats per warp slice

__global__ void __launch_bounds__(NTHR, 1)
lstm_kernel(const float* __restrict__ states,
            const float* __restrict__ Wx0, const float* __restrict__ R0, const float* __restrict__ bias0,
            const float* __restrict__ Wx1, const float* __restrict__ R1, const float* __restrict__ bias1,
            float* __restrict__ out)
{
    __shared__ float red[2][8 * REDW];

    const int tid  = threadIdx.x;
    const int wid  = tid >> 5;
    const int lane = tid & 31;
    const int gid  = lane >> 2;   // mma group id (row)
    const int tig  = lane & 3;    // mma thread-in-group (col/k)
    const int cta  = blockIdx.x;
    const int kbase = wid * 96;   // this warp's K slice -> producer CTAs [12*wid, 12*wid+12)

    // epilogue mapping: tid<128 -> b = tid>>3, e_l = tid&7; e_global = cta*8 + e_l
    const int eb = tid >> 3;
    const int el = tid & 7;
    const int eg = cta * 8 + el;

    // poll target: lanes 0-11 each watch one producer CTA's flag (own 128B line)
    const int* poll_fp = g_flag + (12 * wid + (lane < 12 ? lane : 0)) * 32;

    // register-resident state
    uint32_t areg[2][6][4];       // A fragments: [m-tile][k-tile][reg]
    float    biasL[2][4];         // both layers' biases, preloaded
    float    creg = 0.f;
    float    wxc[4], wxn[4];      // Wx pipeline (current / next step)

    if (tid < 128) {
        creg = states[NBATCH * DHID + eb * DHID + eg];
        #pragma unroll
        for (int g = 0; g < 4; ++g) {
            biasL[0][g] = __ldg(bias0 + g * DHID + eg);
            biasL[1][g] = __ldg(bias1 + g * DHID + eg);
        }
        // Wx for step 0
        const float* wp = Wx0 + (size_t)eb * (TLEN * 4 * DHID) + eg;
        #pragma unroll
        for (int g = 0; g < 4; ++g)
            wxc[g] = __ldcs(wp + g * DHID);
    }

    for (int s = 0; s < NSTEP; ++s) {
        const int layer = s >> 10;
        const int t     = s & 1023;

        // ---- per-layer setup: load A fragments (R slice) into registers ----
        if (t == 0) {
            const float* R = layer ? R1 : R0;
            #pragma unroll
            for (int mt = 0; mt < 2; ++mt) {
                const int r0 = mt * 16 + gid;      // local rows r0, r0+8
                const int r1 = r0 + 8;
                const int g0 = r0 >> 3, e0 = cta * 8 + (r0 & 7);
                const int g1 = r1 >> 3, e1 = cta * 8 + (r1 & 7);
                const float* p0 = R + (size_t)g0 * (DHID * DHID) + e0;
                const float* p1 = R + (size_t)g1 * (DHID * DHID) + e1;
                #pragma unroll
                for (int kt = 0; kt < 6; ++kt) {
                    const int k0 = kbase + kt * 16 + tig * 2;
                    areg[mt][kt][0] = pack_h2(__ldg(p0 + (size_t)(k0    ) * DHID),
                                              __ldg(p0 + (size_t)(k0 + 1) * DHID));
                    areg[mt][kt][1] = pack_h2(__ldg(p1 + (size_t)(k0    ) * DHID),
                                              __ldg(p1 + (size_t)(k0 + 1) * DHID));
                    areg[mt][kt][2] = pack_h2(__ldg(p0 + (size_t)(k0 + 8) * DHID),
                                              __ldg(p0 + (size_t)(k0 + 9) * DHID));
                    areg[mt][kt][3] = pack_h2(__ldg(p1 + (size_t)(k0 + 8) * DHID),
                                              __ldg(p1 + (size_t)(k0 + 9) * DHID));
                }
            }
        }

        // ---- deep Wx prefetch: issue step s+1's loads NOW (full step of cover) ----
        if (tid < 128 && s + 1 < NSTEP) {
            const int l1 = (s + 1) >> 10;
            const int t1 = (s + 1) & 1023;
            const float* Wx = l1 ? Wx1 : Wx0;
            const float* wp = Wx + (size_t)eb * (TLEN * 4 * DHID) + (size_t)t1 * 3072 + eg;
            #pragma unroll
            for (int g = 0; g < 4; ++g)
                wxn[g] = __ldcs(wp + g * DHID);
        }

        // ---- per-warp wait: this warp's 12 producer CTAs ----
        if (s > 0) {
            unsigned ok = (lane < 12) ? 0u : 1u;
            while (__ballot_sync(0xffffffffu, ok) != 0xffffffffu) {
                if (!ok) {
                    unsigned v;
                    asm volatile("ld.acquire.gpu.global.u32 %0, [%1];"
                                 : "=r"(v) : "l"(poll_fp) : "memory");
                    ok = (v >= (unsigned)s) ? 1u : 0u;
                }
            }
        }

        // ---- B fragments straight from global h buffer (L2, coherent) ----
        const __half* hb = g_hbuf[s & 1];
        uint32_t bf[6][2][2];
        #pragma unroll
        for (int kt = 0; kt < 6; ++kt) {
            const int k0 = kbase + kt * 16 + tig * 2;
            #pragma unroll
            for (int nt = 0; nt < 2; ++nt) {
                const __half* hp = hb + (nt * 8 + gid) * DHID + k0;
                bf[kt][nt][0] = ldcg_b32(hp);
                bf[kt][nt][1] = ldcg_b32(hp + 8);
            }
        }

        // ---- MMA: partial D[32,16] over this warp's K slice ----
        float acc[2][2][4];
        #pragma unroll
        for (int mt = 0; mt < 2; ++mt)
            #pragma unroll
            for (int nt = 0; nt < 2; ++nt)
                #pragma unroll
                for (int r = 0; r < 4; ++r)
                    acc[mt][nt][r] = 0.f;
        #pragma unroll
        for (int kt = 0; kt < 6; ++kt)
            #pragma unroll
            for (int mt = 0; mt < 2; ++mt)
                #pragma unroll
                for (int nt = 0; nt < 2; ++nt)
                    mma16816(acc[mt][nt], areg[mt][kt], bf[kt][nt]);

        // ---- partials to SMEM (parity buffer) for cross-warp K reduction ----
        {
            float* rp = red[s & 1] + wid * REDW;
            #pragma unroll
            for (int mt = 0; mt < 2; ++mt) {
                const int l0 = mt * 16 + gid;
                #pragma unroll
                for (int nt = 0; nt < 2; ++nt) {
                    const int n0 = nt * 8 + tig * 2;
                    rp[(l0    ) * 17 + n0    ] = acc[mt][nt][0];
                    rp[(l0    ) * 17 + n0 + 1] = acc[mt][nt][1];
                    rp[(l0 + 8) * 17 + n0    ] = acc[mt][nt][2];
                    rp[(l0 + 8) * 17 + n0 + 1] = acc[mt][nt][3];
                }
            }
        }
        // single CTA barrier per step: partials visible; union of the 8 warps'
        // waits == all 96 CTAs published step s -> safe to overwrite h[(s+1)&1].
        __syncthreads();

        // ---- epilogue (warps 0-3): reduce, activations, cell update, publish ----
        if (tid < 128) {
            const float* rb = red[s & 1];
            float gate[4];
            #pragma unroll
            for (int g = 0; g < 4; ++g) {
                float v = wxc[g] + biasL[layer][g];
                const int li = g * 8 + el;
                #pragma unroll
                for (int w = 0; w < 8; ++w)
                    v += rb[w * REDW + li * 17 + eb];
                gate[g] = v;
            }
            const float iv = fast_sigmoid(gate[0]);
            const float fv = fast_sigmoid(gate[1]);
            const float zv = fast_tanh(gate[2]);
            const float ov = fast_sigmoid(gate[3]);
            creg = fv * creg + iv * zv;
            const float hv = ov * fast_tanh(creg);

            // h broadcast for next step (must precede the flag release)
            __half* hp = &g_hbuf[(s + 1) & 1][eb * DHID + eg];
            asm volatile("st.global.cg.b16 [%0], %1;"
                         :: "l"(hp), "h"(__half_as_ushort(__float2half_rn(hv))) : "memory");

            // epilogue-warps barrier, then single-writer release of this CTA's flag
            asm volatile("bar.sync 1, 128;" ::: "memory");
            if (tid == 0) {
                asm volatile("st.release.gpu.global.u32 [%0], %1;"
                             :: "l"(g_flag + cta * 32), "r"(s + 1) : "memory");
            }

            // layer-2 outputs: streaming stores AFTER the release (off the chain)
            if (layer) {
                float* po = out + (size_t)t * 24576 + eb * DHID + eg;
                __stcs(po,         hv);
                __stcs(po + 12288, creg);
                if (t == TLEN - 1) {
                    float* pl = out + (size_t)25165824 + eb * DHID + eg;
                    __stcs(pl,                 hv);    // last_h: h
                    __stcs(pl + 12288,         creg);  // last_h: c
                    __stcs(pl + 24576,         hv);    // out: h
                    __stcs(pl + 24576 + 12288, creg);  // out: c
                }
            }

            // rotate the Wx pipeline
            #pragma unroll
            for (int g = 0; g < 4; ++g) wxc[g] = wxn[g];
        }
        // no tail barrier: red[] is parity double-buffered
    }
}

extern "C" void kernel_launch(void* const* d_in, const int* in_sizes, int n_in,
                              void* d_out, int out_size) {
    (void)in_sizes; (void)n_in; (void)out_size;
    const float* states = (const float*)d_in[0];
    const float* Wx0    = (const float*)d_in[1];
    const float* R0     = (const float*)d_in[2];
    const float* b0     = (const float*)d_in[3];
    const float* Wx1    = (const float*)d_in[4];
    const float* R1     = (const float*)d_in[5];
    const float* b1     = (const float*)d_in[6];
    float* out = (float*)d_out;

    init_kernel<<<48, 256>>>(states);
    lstm_kernel<<<NCTA, NTHR>>>(states, Wx0, R0, b0, Wx1, R1, b1, out);
}

// round 16
// speedup vs baseline: 1.3604x; 1.1976x over previous
#include <cuda_runtime.h>
#include <cuda_fp16.h>
#include <cstdint>

#define NBATCH 16
#define TLEN   1024
#define DHID   768
#define NCTA   96
#define CPG    48      // CTAs per sync group
#define BPG    8       // batches per group
#define NSTEP  2048
#define NTHR   256

// ---------------- global scratch (no device allocation allowed) ----------------
__device__ __align__(16) __half g_hbuf[2][NBATCH * DHID];  // h double buffer, fp16 [b][d]
__device__ int g_flag[NCTA * 32];                          // one flag per CTA, one per 128B line

__global__ void init_kernel(const float* __restrict__ states) {
    int i = blockIdx.x * blockDim.x + threadIdx.x;
    if (i < NBATCH * DHID) g_hbuf[0][i] = __float2half_rn(states[i]);
    if (i < NCTA * 32) g_flag[i] = 0;
}

// ---------------- helpers ----------------
__device__ __forceinline__ float fast_sigmoid(float x) {
    return 1.f / (1.f + __expf(-x));
}
__device__ __forceinline__ float fast_tanh(float x) {
    float ax = fabsf(x);
    float e  = __expf(-2.f * ax);
    float r  = (1.f - e) / (1.f + e);
    return copysignf(r, x);
}
__device__ __forceinline__ uint32_t ldcg_b32(const void* p) {
    uint32_t v;
    asm volatile("ld.global.cg.b32 %0, [%1];" : "=r"(v) : "l"(p));
    return v;
}
__device__ __forceinline__ uint32_t pack_h2(float lo, float hi) {
    __half2 h = __floats2half2_rn(lo, hi);
    return *reinterpret_cast<uint32_t*>(&h);
}
__device__ __forceinline__ void mma16816(float* d, const uint32_t* a, const uint32_t* b) {
    asm volatile(
        "mma.sync.aligned.m16n8k16.row.col.f32.f16.f16.f32 "
        "{%0,%1,%2,%3}, {%4,%5,%6,%7}, {%8,%9}, {%0,%1,%2,%3};"
        : "+f"(d[0]), "+f"(d[1]), "+f"(d[2]), "+f"(d[3])
        : "r"(a[0]), "r"(a[1]), "r"(a[2]), "r"(a[3]), "r"(b[0]), "r"(b[1]));
}

// red[parity][w][l][b]: 8 warps, 64 local gate-rows, batch padded to 9
#define REDW 576   // 64*9 floats per warp slice

__global__ void __launch_bounds__(NTHR, 1)
lstm_kernel(const float* __restrict__ states,
            const float* __restrict__ Wx0, const float* __restrict__ R0, const float* __restrict__ bias0,
            const float* __restrict__ Wx1, const float* __restrict__ R1, const float* __restrict__ bias1,
            float* __restrict__ out)
{
    __shared__ float red[2][8 * REDW];   // 36864 B

    const int tid  = threadIdx.x;
    const int wid  = tid >> 5;
    const int lane = tid & 31;
    const int gid  = lane >> 2;   // mma group id
    const int tig  = lane & 3;    // thread-in-group
    const int bx   = blockIdx.x;
    const int group = bx / CPG;   // sync domain (batches group*8 .. group*8+7)
    const int cid   = bx - group * CPG;
    const int E0    = cid * 16;   // this CTA's 16 hidden dims
    const int kbase = wid * 96;   // K slice -> producer cids [6*wid, 6*wid+6)

    // epilogue mapping (tid<128): eb = batch-in-group, el = local dim
    const int eb    = tid >> 4;
    const int el    = tid & 15;
    const int bglob = group * BPG + eb;
    const int eg    = E0 + el;

    // poll target: lanes 0-5 each watch one producer CTA's flag line
    const int* poll_fp = g_flag + (group * CPG + 6 * wid + (lane < 6 ? lane : 0)) * 32;

    // register-resident state
    uint32_t areg[4][6][4];       // A fragments: [m-tile][k-tile][reg]
    float    biasL[2][4];
    float    creg = 0.f;
    float    wxc[4], wxn[4];

    if (tid < 128) {
        creg = states[NBATCH * DHID + bglob * DHID + eg];
        #pragma unroll
        for (int g = 0; g < 4; ++g) {
            biasL[0][g] = __ldg(bias0 + g * DHID + eg);
            biasL[1][g] = __ldg(bias1 + g * DHID + eg);
        }
        const float* wp = Wx0 + (size_t)bglob * (TLEN * 4 * DHID) + eg;
        #pragma unroll
        for (int g = 0; g < 4; ++g)
            wxc[g] = __ldcs(wp + g * DHID);
    }

    for (int s = 0; s < NSTEP; ++s) {
        const int layer = s >> 10;
        const int t     = s & 1023;

        // ---- per-layer setup: load A fragments (R slice) into registers ----
        if (t == 0) {
            const float* R = layer ? R1 : R0;
            #pragma unroll
            for (int mt = 0; mt < 4; ++mt) {
                const int l0 = mt * 16 + gid;      // local rows l0, l0+8 (of 64)
                const int l1 = l0 + 8;
                const int g0 = l0 >> 4, e0 = E0 + (l0 & 15);
                const int g1 = l1 >> 4, e1 = E0 + (l1 & 15);
                const float* p0 = R + (size_t)g0 * (DHID * DHID) + e0;
                const float* p1 = R + (size_t)g1 * (DHID * DHID) + e1;
                #pragma unroll
                for (int kt = 0; kt < 6; ++kt) {
                    const int k0 = kbase + kt * 16 + tig * 2;
                    areg[mt][kt][0] = pack_h2(__ldg(p0 + (size_t)(k0    ) * DHID),
                                              __ldg(p0 + (size_t)(k0 + 1) * DHID));
                    areg[mt][kt][1] = pack_h2(__ldg(p1 + (size_t)(k0    ) * DHID),
                                              __ldg(p1 + (size_t)(k0 + 1) * DHID));
                    areg[mt][kt][2] = pack_h2(__ldg(p0 + (size_t)(k0 + 8) * DHID),
                                              __ldg(p0 + (size_t)(k0 + 9) * DHID));
                    areg[mt][kt][3] = pack_h2(__ldg(p1 + (size_t)(k0 + 8) * DHID),
                                              __ldg(p1 + (size_t)(k0 + 9) * DHID));
                }
            }
        }

        // ---- deep Wx prefetch for step s+1 (full step of latency cover) ----
        if (tid < 128 && s + 1 < NSTEP) {
            const int l1 = (s + 1) >> 10;
            const int t1 = (s + 1) & 1023;
            const float* Wx = l1 ? Wx1 : Wx0;
            const float* wp = Wx + (size_t)bglob * (TLEN * 4 * DHID) + (size_t)t1 * 3072 + eg;
            #pragma unroll
            for (int g = 0; g < 4; ++g)
                wxn[g] = __ldcs(wp + g * DHID);
        }

        // ---- per-warp wait: this warp's 6 producer CTAs (own domain only) ----
        if (s > 0) {
            unsigned ok = (lane < 6) ? 0u : 1u;
            while (__ballot_sync(0xffffffffu, ok) != 0xffffffffu) {
                if (!ok) {
                    unsigned v;
                    asm volatile("ld.acquire.gpu.global.u32 %0, [%1];"
                                 : "=r"(v) : "l"(poll_fp) : "memory");
                    ok = (v >= (unsigned)s) ? 1u : 0u;
                }
            }
        }

        // ---- B fragments: this domain's 8 batches from global h buffer ----
        const __half* hb = g_hbuf[s & 1];
        uint32_t bf[6][2];
        #pragma unroll
        for (int kt = 0; kt < 6; ++kt) {
            const int k0 = kbase + kt * 16 + tig * 2;
            const __half* hp = hb + (size_t)(group * BPG + gid) * DHID + k0;
            bf[kt][0] = ldcg_b32(hp);
            bf[kt][1] = ldcg_b32(hp + 8);
        }

        // ---- MMA: partial D[64,8] over this warp's K slice ----
        float acc[4][4];
        #pragma unroll
        for (int mt = 0; mt < 4; ++mt)
            #pragma unroll
            for (int r = 0; r < 4; ++r)
                acc[mt][r] = 0.f;
        #pragma unroll
        for (int kt = 0; kt < 6; ++kt)
            #pragma unroll
            for (int mt = 0; mt < 4; ++mt)
                mma16816(acc[mt], areg[mt][kt], bf[kt]);

        // ---- partials to SMEM (parity buffer) for cross-warp K reduction ----
        {
            float* rp = red[s & 1] + wid * REDW;
            const int n0 = tig * 2;
            #pragma unroll
            for (int mt = 0; mt < 4; ++mt) {
                const int l0 = mt * 16 + gid;
                rp[(l0    ) * 9 + n0    ] = acc[mt][0];
                rp[(l0    ) * 9 + n0 + 1] = acc[mt][1];
                rp[(l0 + 8) * 9 + n0    ] = acc[mt][2];
                rp[(l0 + 8) * 9 + n0 + 1] = acc[mt][3];
            }
        }
        // one barrier per step: partials visible; union of the 8 warps' waits
        // == all 48 domain CTAs published step s -> safe to overwrite h[(s+1)&1].
        __syncthreads();

        // ---- epilogue (warps 0-3): reduce, activations, cell update, publish ----
        if (tid < 128) {
            const float* rb = red[s & 1];
            float gate[4];
            #pragma unroll
            for (int g = 0; g < 4; ++g) {
                float v = wxc[g] + biasL[layer][g];
                const int li = g * 16 + el;
                #pragma unroll
                for (int w = 0; w < 8; ++w)
                    v += rb[w * REDW + li * 9 + eb];
                gate[g] = v;
            }
            const float iv = fast_sigmoid(gate[0]);
            const float fv = fast_sigmoid(gate[1]);
            const float zv = fast_tanh(gate[2]);
            const float ov = fast_sigmoid(gate[3]);
            creg = fv * creg + iv * zv;
            const float hv = ov * fast_tanh(creg);

            // h broadcast for next step (precedes the flag release)
            __half* hp = &g_hbuf[(s + 1) & 1][(size_t)bglob * DHID + eg];
            asm volatile("st.global.cg.b16 [%0], %1;"
                         :: "l"(hp), "h"(__half_as_ushort(__float2half_rn(hv))) : "memory");

            // epilogue-warps barrier, then single-writer release of this CTA's flag
            asm volatile("bar.sync 1, 128;" ::: "memory");
            if (tid == 0) {
                asm volatile("st.release.gpu.global.u32 [%0], %1;"
                             :: "l"(g_flag + bx * 32), "r"(s + 1) : "memory");
            }

            // layer-2 outputs: streaming stores AFTER the release (off the chain)
            if (layer) {
                float* po = out + (size_t)t * 24576 + (size_t)bglob * DHID + eg;
                __stcs(po,         hv);
                __stcs(po + 12288, creg);
                if (t == TLEN - 1) {
                    float* pl = out + (size_t)25165824 + (size_t)bglob * DHID + eg;
                    __stcs(pl,                 hv);    // last_h: h
                    __stcs(pl + 12288,         creg);  // last_h: c
                    __stcs(pl + 24576,         hv);    // out: h
                    __stcs(pl + 24576 + 12288, creg);  // out: c
                }
            }

            // rotate the Wx pipeline
            #pragma unroll
            for (int g = 0; g < 4; ++g) wxc[g] = wxn[g];
        }
        // no tail barrier: red[] is parity double-buffered
    }
}

extern "C" void kernel_launch(void* const* d_in, const int* in_sizes, int n_in,
                              void* d_out, int out_size) {
    (void)in_sizes; (void)n_in; (void)out_size;
    const float* states = (const float*)d_in[0];
    const float* Wx0    = (const float*)d_in[1];
    const float* R0     = (const float*)d_in[2];
    const float* b0     = (const float*)d_in[3];
    const float* Wx1    = (const float*)d_in[4];
    const float* R1     = (const float*)d_in[5];
    const float* b1     = (const float*)d_in[6];
    float* out = (float*)d_out;

    init_kernel<<<48, 256>>>(states);
    lstm_kernel<<<NCTA, NTHR>>>(states, Wx0, R0, b0, Wx1, R1, b1, out);
}

// round 17
// speedup vs baseline: 1.3972x; 1.0271x over previous
#include <cuda_runtime.h>
#include <cuda_fp16.h>
#include <cstdint>

#define NBATCH 16
#define TLEN   1024
#define DHID   768
#define NCTA   128
#define CPG    32      // CTAs per sync domain
#define BPG    4       // batches per domain
#define DIMS_PER_CTA 24
#define NSTEP  2048
#define NTHR   256

// ---------------- global scratch (no device allocation allowed) ----------------
__device__ __align__(16) __half g_hbuf[2][NBATCH * DHID];  // h double buffer, fp16 [b][d]
__device__ int g_flag[NCTA * 32];                          // one flag per CTA, one per 128B line

__global__ void init_kernel(const float* __restrict__ states) {
    int i = blockIdx.x * blockDim.x + threadIdx.x;
    if (i < NBATCH * DHID) g_hbuf[0][i] = __float2half_rn(states[i]);
    if (i < NCTA * 32) g_flag[i] = 0;
}

// ---------------- helpers ----------------
__device__ __forceinline__ float fast_sigmoid(float x) {
    return 1.f / (1.f + __expf(-x));
}
__device__ __forceinline__ float fast_tanh(float x) {
    float ax = fabsf(x);
    float e  = __expf(-2.f * ax);
    float r  = (1.f - e) / (1.f + e);
    return copysignf(r, x);
}
__device__ __forceinline__ uint32_t ldcg_b32(const void* p) {
    uint32_t v;
    asm volatile("ld.global.cg.b32 %0, [%1];" : "=r"(v) : "l"(p));
    return v;
}
__device__ __forceinline__ uint32_t pack_h2(float lo, float hi) {
    __half2 h = __floats2half2_rn(lo, hi);
    return *reinterpret_cast<uint32_t*>(&h);
}
__device__ __forceinline__ void mma16816(float* d, const uint32_t* a, const uint32_t* b) {
    asm volatile(
        "mma.sync.aligned.m16n8k16.row.col.f32.f16.f16.f32 "
        "{%0,%1,%2,%3}, {%4,%5,%6,%7}, {%8,%9}, {%0,%1,%2,%3};"
        : "+f"(d[0]), "+f"(d[1]), "+f"(d[2]), "+f"(d[3])
        : "r"(a[0]), "r"(a[1]), "r"(a[2]), "r"(a[3]), "r"(b[0]), "r"(b[1]));
}

// red[parity][w][l][b]: 8 warps, 96 local gate-rows, batch (0..3) padded to 5
#define REDW 480   // 96*5 floats per warp slice

__global__ void __launch_bounds__(NTHR, 1)
lstm_kernel(const float* __restrict__ states,
            const float* __restrict__ Wx0, const float* __restrict__ R0, const float* __restrict__ bias0,
            const float* __restrict__ Wx1, const float* __restrict__ R1, const float* __restrict__ bias1,
            float* __restrict__ out)
{
    __shared__ float red[2][8 * REDW];   // 30720 B

    const int tid  = threadIdx.x;
    const int wid  = tid >> 5;
    const int lane = tid & 31;
    const int gid  = lane >> 2;   // mma group id
    const int tig  = lane & 3;    // thread-in-group
    const int bx   = blockIdx.x;
    const int dom  = bx / CPG;    // sync domain (batches dom*4 .. dom*4+3)
    const int cid  = bx - dom * CPG;
    const int E0   = cid * DIMS_PER_CTA;   // this CTA's 24 hidden dims
    const int kbase = wid * 96;   // K slice -> producer cids [4*wid, 4*wid+4)

    // epilogue mapping (tid<96): eb = batch-in-domain, el = local dim
    const int eb    = tid / DIMS_PER_CTA;          // 0..3 for tid<96
    const int el    = tid - eb * DIMS_PER_CTA;     // 0..23
    const int bglob = dom * BPG + eb;
    const int eg    = E0 + el;

    // poll target: lanes 0-3 each watch one producer CTA's flag line
    const int* poll_fp = g_flag + (dom * CPG + 4 * wid + (lane < 4 ? lane : 0)) * 32;

    // register-resident state
    uint32_t areg[6][6][4];       // A fragments: [m-tile][k-tile][reg]
    float    biasL[2][4];
    float    creg = 0.f;
    float    wxc[4], wxn[4];

    if (tid < 96) {
        creg = states[NBATCH * DHID + bglob * DHID + eg];
        #pragma unroll
        for (int g = 0; g < 4; ++g) {
            biasL[0][g] = __ldg(bias0 + g * DHID + eg);
            biasL[1][g] = __ldg(bias1 + g * DHID + eg);
        }
        const float* wp = Wx0 + (size_t)bglob * (TLEN * 4 * DHID) + eg;
        #pragma unroll
        for (int g = 0; g < 4; ++g)
            wxc[g] = __ldcs(wp + g * DHID);
    }

    for (int s = 0; s < NSTEP; ++s) {
        const int layer = s >> 10;
        const int t     = s & 1023;

        // ---- per-layer setup: load A fragments (R slice) into registers ----
        if (t == 0) {
            const float* R = layer ? R1 : R0;
            #pragma unroll
            for (int mt = 0; mt < 6; ++mt) {
                const int l0 = mt * 16 + gid;      // local rows l0, l0+8 (of 96)
                const int l1 = l0 + 8;
                const int g0 = l0 / DIMS_PER_CTA, e0 = E0 + (l0 - g0 * DIMS_PER_CTA);
                const int g1 = l1 / DIMS_PER_CTA, e1 = E0 + (l1 - g1 * DIMS_PER_CTA);
                const float* p0 = R + (size_t)g0 * (DHID * DHID) + e0;
                const float* p1 = R + (size_t)g1 * (DHID * DHID) + e1;
                #pragma unroll
                for (int kt = 0; kt < 6; ++kt) {
                    const int k0 = kbase + kt * 16 + tig * 2;
                    areg[mt][kt][0] = pack_h2(__ldg(p0 + (size_t)(k0    ) * DHID),
                                              __ldg(p0 + (size_t)(k0 + 1) * DHID));
                    areg[mt][kt][1] = pack_h2(__ldg(p1 + (size_t)(k0    ) * DHID),
                                              __ldg(p1 + (size_t)(k0 + 1) * DHID));
                    areg[mt][kt][2] = pack_h2(__ldg(p0 + (size_t)(k0 + 8) * DHID),
                                              __ldg(p0 + (size_t)(k0 + 9) * DHID));
                    areg[mt][kt][3] = pack_h2(__ldg(p1 + (size_t)(k0 + 8) * DHID),
                                              __ldg(p1 + (size_t)(k0 + 9) * DHID));
                }
            }
        }

        // ---- deep Wx prefetch for step s+1 (full step of latency cover) ----
        if (tid < 96 && s + 1 < NSTEP) {
            const int l1 = (s + 1) >> 10;
            const int t1 = (s + 1) & 1023;
            const float* Wx = l1 ? Wx1 : Wx0;
            const float* wp = Wx + (size_t)bglob * (TLEN * 4 * DHID) + (size_t)t1 * 3072 + eg;
            #pragma unroll
            for (int g = 0; g < 4; ++g)
                wxn[g] = __ldcs(wp + g * DHID);
        }

        // ---- per-warp wait: this warp's 4 producer CTAs (own domain only) ----
        if (s > 0) {
            unsigned ok = (lane < 4) ? 0u : 1u;
            while (__ballot_sync(0xffffffffu, ok) != 0xffffffffu) {
                if (!ok) {
                    unsigned v;
                    asm volatile("ld.acquire.gpu.global.u32 %0, [%1];"
                                 : "=r"(v) : "l"(poll_fp) : "memory");
                    ok = (v >= (unsigned)s) ? 1u : 0u;
                }
            }
        }

        // ---- B fragments: this domain's 4 batches (rows 4-7 duplicate 0-3) ----
        const __half* hb = g_hbuf[s & 1];
        uint32_t bf[6][2];
        {
            const __half* hrow = hb + (size_t)(dom * BPG + (gid & 3)) * DHID;
            #pragma unroll
            for (int kt = 0; kt < 6; ++kt) {
                const int k0 = kbase + kt * 16 + tig * 2;
                bf[kt][0] = ldcg_b32(hrow + k0);
                bf[kt][1] = ldcg_b32(hrow + k0 + 8);
            }
        }

        // ---- MMA: partial D[96,8] over this warp's K slice ----
        float acc[6][4];
        #pragma unroll
        for (int mt = 0; mt < 6; ++mt)
            #pragma unroll
            for (int r = 0; r < 4; ++r)
                acc[mt][r] = 0.f;
        #pragma unroll
        for (int kt = 0; kt < 6; ++kt)
            #pragma unroll
            for (int mt = 0; mt < 6; ++mt)
                mma16816(acc[mt], areg[mt][kt], bf[kt]);

        // ---- partials to SMEM (parity buffer); only cols 0-3 are real ----
        if (tig < 2) {
            float* rp = red[s & 1] + wid * REDW;
            const int n0 = tig * 2;
            #pragma unroll
            for (int mt = 0; mt < 6; ++mt) {
                const int l0 = mt * 16 + gid;
                rp[(l0    ) * 5 + n0    ] = acc[mt][0];
                rp[(l0    ) * 5 + n0 + 1] = acc[mt][1];
                rp[(l0 + 8) * 5 + n0    ] = acc[mt][2];
                rp[(l0 + 8) * 5 + n0 + 1] = acc[mt][3];
            }
        }
        // one barrier per step: partials visible; union of the 8 warps' waits
        // == all 32 domain CTAs published step s -> safe to overwrite h[(s+1)&1].
        __syncthreads();

        // ---- epilogue (tid<96): reduce, activations, cell update, publish ----
        if (tid < 96) {
            const float* rb = red[s & 1];
            float gate[4];
            #pragma unroll
            for (int g = 0; g < 4; ++g) {
                float v = wxc[g] + biasL[layer][g];
                const int li = g * DIMS_PER_CTA + el;
                #pragma unroll
                for (int w = 0; w < 8; ++w)
                    v += rb[w * REDW + li * 5 + eb];
                gate[g] = v;
            }
            const float iv = fast_sigmoid(gate[0]);
            const float fv = fast_sigmoid(gate[1]);
            const float zv = fast_tanh(gate[2]);
            const float ov = fast_sigmoid(gate[3]);
            creg = fv * creg + iv * zv;
            const float hv = ov * fast_tanh(creg);

            // h broadcast for next step (precedes the flag release)
            __half* hp = &g_hbuf[(s + 1) & 1][(size_t)bglob * DHID + eg];
            asm volatile("st.global.cg.b16 [%0], %1;"
                         :: "l"(hp), "h"(__half_as_ushort(__float2half_rn(hv))) : "memory");

            // epilogue-warps barrier (warps 0-2), then single-writer release
            asm volatile("bar.sync 1, 96;" ::: "memory");
            if (tid == 0) {
                asm volatile("st.release.gpu.global.u32 [%0], %1;"
                             :: "l"(g_flag + bx * 32), "r"(s + 1) : "memory");
            }

            // layer-2 outputs: streaming stores AFTER the release (off the chain)
            if (layer) {
                float* po = out + (size_t)t * 24576 + (size_t)bglob * DHID + eg;
                __stcs(po,         hv);
                __stcs(po + 12288, creg);
                if (t == TLEN - 1) {
                    float* pl = out + (size_t)25165824 + (size_t)bglob * DHID + eg;
                    __stcs(pl,                 hv);    // last_h: h
                    __stcs(pl + 12288,         creg);  // last_h: c
                    __stcs(pl + 24576,         hv);    // out: h
                    __stcs(pl + 24576 + 12288, creg);  // out: c
                }
            }

            // rotate the Wx pipeline
            #pragma unroll
            for (int g = 0; g < 4; ++g) wxc[g] = wxn[g];
        }
        // no tail barrier: red[] is parity double-buffered
    }
}

extern "C" void kernel_launch(void* const* d_in, const int* in_sizes, int n_in,
                              void* d_out, int out_size) {
    (void)in_sizes; (void)n_in; (void)out_size;
    const float* states = (const float*)d_in[0];
    const float* Wx0    = (const float*)d_in[1];
    const float* R0     = (const float*)d_in[2];
    const float* b0     = (const float*)d_in[3];
    const float* Wx1    = (const float*)d_in[4];
    const float* R1     = (const float*)d_in[5];
    const float* b1     = (const float*)d_in[6];
    float* out = (float*)d_out;

    init_kernel<<<48, 256>>>(states);
    lstm_kernel<<<NCTA, NTHR>>>(states, Wx0, R0, b0, Wx1, R1, b1, out);
}